// round 2
// baseline (speedup 1.0000x reference)
#include <cuda_runtime.h>
#include <cuda_fp16.h>
#include <cstdint>
#include <cstddef>

#define NROW   200000
#define CIN    64
#define COUT   64
#define KOFF   27
#define TILE_M 128
#define NTILES ((NROW + TILE_M - 1) / TILE_M)   // 1563

// ---------------- device scratch (no allocs allowed) ----------------
__device__ __align__(128) __half g_feats16[(NROW + 8) * CIN];   // row NROW = zeros
__device__ __align__(128) __half g_w16[KOFF * CIN * COUT];      // [k][cin][cout] (same layout as W)
__device__ int    g_idx2[KOFF * NROW];                          // masked indices
__device__ float  g_conv[(size_t)NROW * COUT];                  // conv output scratch
__device__ float  g_partials[NTILES * 128];                     // per-tile {sum[64], sumsq[64]}
__device__ float  g_bn[128];                                    // {scale[64], shift[64]}

// ---------------- helpers ----------------
__device__ __forceinline__ uint32_t smem_u32(const void* p) {
    uint32_t a;
    asm("{ .reg .u64 t; cvta.to.shared.u64 t, %1; cvt.u32.u64 %0, t; }" : "=r"(a) : "l"(p));
    return a;
}

__device__ __forceinline__ void cp_async16(uint32_t dst, const void* src) {
    asm volatile("cp.async.cg.shared.global [%0], [%1], 16;" :: "r"(dst), "l"(src));
}
__device__ __forceinline__ void cp_commit() {
    asm volatile("cp.async.commit_group;" ::: "memory");
}

__device__ __forceinline__ void ldmatrix_x4(uint32_t* r, uint32_t addr) {
    asm volatile("ldmatrix.sync.aligned.m8n8.x4.shared.b16 {%0,%1,%2,%3}, [%4];"
                 : "=r"(r[0]), "=r"(r[1]), "=r"(r[2]), "=r"(r[3]) : "r"(addr));
}
__device__ __forceinline__ void ldmatrix_x4_t(uint32_t* r, uint32_t addr) {
    asm volatile("ldmatrix.sync.aligned.m8n8.x4.trans.shared.b16 {%0,%1,%2,%3}, [%4];"
                 : "=r"(r[0]), "=r"(r[1]), "=r"(r[2]), "=r"(r[3]) : "r"(addr));
}

__device__ __forceinline__ void mma16816(float* d, const uint32_t* a, uint32_t b0, uint32_t b1) {
    asm volatile(
        "mma.sync.aligned.m16n8k16.row.col.f32.f16.f16.f32 "
        "{%0,%1,%2,%3}, {%4,%5,%6,%7}, {%8,%9}, {%0,%1,%2,%3};"
        : "+f"(d[0]), "+f"(d[1]), "+f"(d[2]), "+f"(d[3])
        : "r"(a[0]), "r"(a[1]), "r"(a[2]), "r"(a[3]), "r"(b0), "r"(b1));
}

// ---------------- SMEM layout ----------------
// A: 128 rows x 72 halfs (144B stride, 64 data + 8 pad) -> conflict-free ldmatrix
// B: 64 rows x 72 halfs
#define A_STRIDE 144
#define B_STRIDE 144
#define A_STAGE  (128 * A_STRIDE)   // 18432
#define B_STAGE  (64 * B_STRIDE)    // 9216
#define OFF_A    0
#define OFF_B    (2 * A_STAGE)      // 36864
#define SMEM_BYTES (2 * A_STAGE + 2 * B_STAGE)  // 55296
#define OFF_PS   34816              // epilogue partial sums (after stats area, 33024B)

// ---------------- prep kernels ----------------
__global__ void prep_feats_kernel(const float* __restrict__ feats) {
    int i = blockIdx.x * 256 + threadIdx.x;      // one float4 (4 channels)
    if (i < NROW * (CIN / 4)) {
        float4 v = reinterpret_cast<const float4*>(feats)[i];
        __half2* dst = reinterpret_cast<__half2*>(g_feats16);
        dst[i * 2]     = __floats2half2_rn(v.x, v.y);
        dst[i * 2 + 1] = __floats2half2_rn(v.z, v.w);
    } else if (i < NROW * (CIN / 4) + (CIN / 4)) { // zero row at index NROW
        __half2 z = __float2half2_rn(0.0f);
        __half2* dst = reinterpret_cast<__half2*>(g_feats16);
        dst[i * 2]     = z;
        dst[i * 2 + 1] = z;
    }
}

__global__ void prep_w_kernel(const float* __restrict__ W) {
    int i = blockIdx.x * 256 + threadIdx.x;
    if (i < KOFF * CIN * COUT) g_w16[i] = __float2half_rn(W[i]);
}

__global__ void prep_idx_kernel(const int* __restrict__ nbr, const int* __restrict__ mask) {
    int i = blockIdx.x * 256 + threadIdx.x;
    if (i < KOFF * NROW) g_idx2[i] = mask[i] ? nbr[i] : NROW;   // masked -> zero row
}

// ---------------- main gather-GEMM kernel ----------------
__device__ __forceinline__ void load_stage(uint32_t sb, int m0, int tid, int k) {
    int s = k & 1;
    uint32_t abuf = sb + OFF_A + s * A_STAGE;
    uint32_t bbuf = sb + OFF_B + s * B_STAGE;
    const int* idxk = g_idx2 + k * NROW;
    // A: 128 rows x 8 x 16B chunks -> 1024 chunks / 256 thr = 4 iters
    #pragma unroll
    for (int it = 0; it < 4; it++) {
        int cid = it * 256 + tid;
        int r = cid >> 3, ch = cid & 7;
        int m = m0 + r;
        int src = (m < NROW) ? __ldg(idxk + m) : NROW;
        const char* gsrc = (const char*)g_feats16 + ((size_t)src * (CIN * 2) + ch * 16);
        cp_async16(abuf + (uint32_t)(r * A_STRIDE + ch * 16), gsrc);
    }
    // B: 64 rows x 8 x 16B chunks = 512 / 256 thr = 2 iters
    const char* wsrc = (const char*)g_w16 + (size_t)k * (CIN * COUT * 2);
    #pragma unroll
    for (int it = 0; it < 2; it++) {
        int cid = it * 256 + tid;
        int r = cid >> 3, ch = cid & 7;
        cp_async16(bbuf + (uint32_t)(r * B_STRIDE + ch * 16), wsrc + r * 128 + ch * 16);
    }
    cp_commit();
}

__global__ void __launch_bounds__(256, 2) conv_mma_kernel() {
    extern __shared__ char smem[];
    uint32_t sb = smem_u32(smem);
    int tid = threadIdx.x, lane = tid & 31, wid = tid >> 5;
    int warp_m = wid & 3, warp_n = wid >> 2;   // 4 x 2 warps -> warp tile 32(M) x 32(N)
    int m0 = blockIdx.x * TILE_M;

    float d[2][4][4];
    #pragma unroll
    for (int i = 0; i < 2; i++)
        #pragma unroll
        for (int j = 0; j < 4; j++)
            #pragma unroll
            for (int l = 0; l < 4; l++) d[i][j][l] = 0.f;

    load_stage(sb, m0, tid, 0);

    // per-thread invariant ldmatrix base offsets (within a stage)
    uint32_t a_off = (uint32_t)((warp_m * 32 + (lane & 15)) * A_STRIDE + (lane >> 4) * 16);
    uint32_t b_off = (uint32_t)((lane & 15) * B_STRIDE + warp_n * 64 + (lane >> 4) * 16);

    #pragma unroll 1
    for (int k = 0; k < KOFF; k++) {
        if (k < KOFF - 1) load_stage(sb, m0, tid, k + 1);
        if (k < KOFF - 1) asm volatile("cp.async.wait_group 1;" ::: "memory");
        else              asm volatile("cp.async.wait_group 0;" ::: "memory");
        __syncthreads();

        uint32_t abuf = sb + OFF_A + (k & 1) * A_STAGE;
        uint32_t bbuf = sb + OFF_B + (k & 1) * B_STAGE;
        uint32_t abase = abuf + a_off;
        uint32_t bbase = bbuf + b_off;
        #pragma unroll
        for (int kk = 0; kk < 4; kk++) {      // K = 64 in 4 x k16
            uint32_t a0 = abase + kk * 32;    // 16 halfs = 32B per k-chunk
            uint32_t bk = bbase + kk * 16 * B_STRIDE;
            uint32_t afr[2][4], bfr[2][4];
            ldmatrix_x4(afr[0], a0);
            ldmatrix_x4(afr[1], a0 + 16 * A_STRIDE);
            ldmatrix_x4_t(bfr[0], bk);        // n 0..15 of warp tile
            ldmatrix_x4_t(bfr[1], bk + 32);   // n 16..31
            #pragma unroll
            for (int mi = 0; mi < 2; mi++)
                #pragma unroll
                for (int nn = 0; nn < 4; nn++)
                    mma16816(d[mi][nn], afr[mi],
                             bfr[nn >> 1][(nn & 1) * 2], bfr[nn >> 1][(nn & 1) * 2 + 1]);
        }
        __syncthreads();   // protect buffer reuse by next iteration's loads
    }

    // ---------------- epilogue ----------------
    // smem reused as stats[c][r] (stride 129 floats) + partial sums at OFF_PS
    float* stats = (float*)smem;
    {
        int r0 = warp_m * 32 + (lane >> 2);
        int c0 = warp_n * 32 + (lane & 3) * 2;
        #pragma unroll
        for (int mi = 0; mi < 2; mi++)
            #pragma unroll
            for (int nn = 0; nn < 4; nn++) {
                int r = r0 + mi * 16;
                int c = c0 + nn * 8;
                stats[(c + 0) * 129 + r]     = d[mi][nn][0];
                stats[(c + 1) * 129 + r]     = d[mi][nn][1];
                stats[(c + 0) * 129 + r + 8] = d[mi][nn][2];
                stats[(c + 1) * 129 + r + 8] = d[mi][nn][3];
            }
    }
    __syncthreads();

    // coalesced conv write: 128 rows x 16 float4 = 2048 float4 / 256 thr = 8 iters
    #pragma unroll
    for (int it = 0; it < 8; it++) {
        int idx = it * 256 + tid;
        int r = idx >> 4, c4 = idx & 15;
        int m = m0 + r;
        if (m < NROW) {
            float4 v;
            v.x = stats[(c4 * 4 + 0) * 129 + r];
            v.y = stats[(c4 * 4 + 1) * 129 + r];
            v.z = stats[(c4 * 4 + 2) * 129 + r];
            v.w = stats[(c4 * 4 + 3) * 129 + r];
            reinterpret_cast<float4*>(g_conv + (size_t)m * COUT)[c4] = v;
        }
    }

    // per-tile channel sums (fixed order -> deterministic); rows >= NROW are exact zeros
    {
        int c = tid & 63, part = tid >> 6;     // 64 channels x 4 row-groups of 32
        float s = 0.f, s2 = 0.f;
        #pragma unroll
        for (int i = 0; i < 32; i++) {
            float v = stats[c * 129 + part * 32 + i];
            s += v; s2 += v * v;
        }
        float* ps = (float*)(smem + OFF_PS);
        ps[part * 64 + c]       = s;
        ps[256 + part * 64 + c] = s2;
    }
    __syncthreads();
    if (tid < 64) {
        const float* ps = (const float*)(smem + OFF_PS);
        float S  = ps[tid] + ps[64 + tid] + ps[128 + tid] + ps[192 + tid];
        float S2 = ps[256 + tid] + ps[320 + tid] + ps[384 + tid] + ps[448 + tid];
        g_partials[blockIdx.x * 128 + tid]      = S;
        g_partials[blockIdx.x * 128 + 64 + tid] = S2;
    }
}

// ---------------- BN stats finalize (single block, deterministic) ----------------
__global__ void bn_stats_kernel(const float* __restrict__ gamma, const float* __restrict__ beta) {
    __shared__ float sh[256];
    int tid = threadIdx.x;
    int c = tid & 127, seg = tid >> 7;         // 2 segments over tiles
    const int half = (NTILES + 1) / 2;         // 782
    int lo = seg * half;
    int hi = lo + half; if (hi > NTILES) hi = NTILES;
    float s = 0.f;
    #pragma unroll 4
    for (int t = lo; t < hi; t++) s += g_partials[t * 128 + c];
    sh[tid] = s;
    __syncthreads();
    if (tid < 64) {
        float S  = sh[tid]      + sh[128 + tid];       // fixed order
        float S2 = sh[64 + tid] + sh[192 + tid];
        const float invN = 1.0f / (float)NROW;
        float mean = S * invN;
        float var  = S2 * invN - mean * mean;
        float inv  = rsqrtf(var + 1e-5f);
        float sc   = inv * gamma[tid];
        g_bn[tid]      = sc;
        g_bn[64 + tid] = beta[tid] - mean * sc;
    }
}

// ---------------- BN apply + ReLU ----------------
__global__ void bn_apply_kernel(float* __restrict__ out) {
    int i = blockIdx.x * 256 + threadIdx.x;    // one float4
    if (i >= NROW * (COUT / 4)) return;
    int c = (i & 15) << 2;
    float4 v = reinterpret_cast<const float4*>(g_conv)[i];
    float4 r;
    r.x = fmaxf(fmaf(v.x, __ldg(&g_bn[c + 0]), __ldg(&g_bn[64 + c + 0])), 0.f);
    r.y = fmaxf(fmaf(v.y, __ldg(&g_bn[c + 1]), __ldg(&g_bn[64 + c + 1])), 0.f);
    r.z = fmaxf(fmaf(v.z, __ldg(&g_bn[c + 2]), __ldg(&g_bn[64 + c + 2])), 0.f);
    r.w = fmaxf(fmaf(v.w, __ldg(&g_bn[c + 3]), __ldg(&g_bn[64 + c + 3])), 0.f);
    reinterpret_cast<float4*>(out)[i] = r;
}

// ---------------- launch ----------------
extern "C" void kernel_launch(void* const* d_in, const int* in_sizes, int n_in,
                              void* d_out, int out_size) {
    const float* feats = (const float*)d_in[0];
    const float* W     = (const float*)d_in[1];
    const float* gamma = (const float*)d_in[2];
    const float* beta  = (const float*)d_in[3];
    const int*   nbr   = (const int*)d_in[4];
    const int*   mask  = (const int*)d_in[5];
    float* out = (float*)d_out;

    cudaFuncSetAttribute(conv_mma_kernel, cudaFuncAttributeMaxDynamicSharedMemorySize, SMEM_BYTES);

    prep_feats_kernel<<<(NROW * (CIN / 4) + (CIN / 4) + 255) / 256, 256>>>(feats);
    prep_w_kernel<<<(KOFF * CIN * COUT + 255) / 256, 256>>>(W);
    prep_idx_kernel<<<(KOFF * NROW + 255) / 256, 256>>>(nbr, mask);
    conv_mma_kernel<<<NTILES, 256, SMEM_BYTES>>>();
    bn_stats_kernel<<<1, 256>>>(gamma, beta);
    bn_apply_kernel<<<(NROW * (COUT / 4) + 255) / 256, 256>>>(out);
}

// round 3
// speedup vs baseline: 1.0094x; 1.0094x over previous
#include <cuda_runtime.h>
#include <cuda_fp16.h>
#include <cstdint>
#include <cstddef>

#define NROW   200000
#define CIN    64
#define COUT   64
#define KOFF   27
#define TILE_M 128
#define NTILES ((NROW + TILE_M - 1) / TILE_M)   // 1563

// ---------------- device scratch (no allocs allowed) ----------------
__device__ __align__(128) __half g_feats16[(NROW + 8) * CIN];   // row NROW = zeros
__device__ __align__(128) __half g_w16[KOFF * CIN * COUT];      // [k][cin][cout]
__device__ int    g_idx2[KOFF * NROW];                          // masked indices
__device__ float  g_conv[(size_t)NROW * COUT];                  // conv output scratch
__device__ float  g_partials[NTILES * 128];                     // per-tile {sum[64], sumsq[64]}
__device__ float  g_bn[128];                                    // {scale[64], shift[64]}

// ---------------- helpers ----------------
__device__ __forceinline__ uint32_t smem_u32(const void* p) {
    uint32_t a;
    asm("{ .reg .u64 t; cvta.to.shared.u64 t, %1; cvt.u32.u64 %0, t; }" : "=r"(a) : "l"(p));
    return a;
}

__device__ __forceinline__ void cp_async16(uint32_t dst, const void* src) {
    asm volatile("cp.async.cg.shared.global [%0], [%1], 16;" :: "r"(dst), "l"(src));
}
__device__ __forceinline__ void cp_commit() {
    asm volatile("cp.async.commit_group;" ::: "memory");
}

__device__ __forceinline__ void ldmatrix_x4(uint32_t* r, uint32_t addr) {
    asm volatile("ldmatrix.sync.aligned.m8n8.x4.shared.b16 {%0,%1,%2,%3}, [%4];"
                 : "=r"(r[0]), "=r"(r[1]), "=r"(r[2]), "=r"(r[3]) : "r"(addr));
}
__device__ __forceinline__ void ldmatrix_x4_t(uint32_t* r, uint32_t addr) {
    asm volatile("ldmatrix.sync.aligned.m8n8.x4.trans.shared.b16 {%0,%1,%2,%3}, [%4];"
                 : "=r"(r[0]), "=r"(r[1]), "=r"(r[2]), "=r"(r[3]) : "r"(addr));
}

__device__ __forceinline__ void mma16816(float* d, const uint32_t* a, uint32_t b0, uint32_t b1) {
    asm volatile(
        "mma.sync.aligned.m16n8k16.row.col.f32.f16.f16.f32 "
        "{%0,%1,%2,%3}, {%4,%5,%6,%7}, {%8,%9}, {%0,%1,%2,%3};"
        : "+f"(d[0]), "+f"(d[1]), "+f"(d[2]), "+f"(d[3])
        : "r"(a[0]), "r"(a[1]), "r"(a[2]), "r"(a[3]), "r"(b0), "r"(b1));
}

// ---------------- SMEM layout ----------------
#define A_STRIDE 144                // 64 halfs data + 8 pad -> conflict-free ldmatrix
#define B_STRIDE 144
#define A_STAGE  (128 * A_STRIDE)   // 18432
#define B_STAGE  (64 * B_STRIDE)    // 9216
#define OFF_A    0
#define OFF_B    (2 * A_STAGE)      // 36864
#define SMEM_BYTES (2 * A_STAGE + 2 * B_STAGE)  // 55296
#define OFF_PS   33536              // epilogue partial sums (after stats 33024B)

// ---------------- prep kernels ----------------
__global__ void prep_feats_kernel(const float* __restrict__ feats) {
    int i = blockIdx.x * 256 + threadIdx.x;      // one float4 (4 channels)
    if (i < NROW * (CIN / 4)) {
        float4 v = reinterpret_cast<const float4*>(feats)[i];
        __half2* dst = reinterpret_cast<__half2*>(g_feats16);
        dst[i * 2]     = __floats2half2_rn(v.x, v.y);
        dst[i * 2 + 1] = __floats2half2_rn(v.z, v.w);
    } else if (i < NROW * (CIN / 4) + (CIN / 4)) { // zero row at index NROW
        __half2 z = __float2half2_rn(0.0f);
        __half2* dst = reinterpret_cast<__half2*>(g_feats16);
        dst[i * 2]     = z;
        dst[i * 2 + 1] = z;
    }
}

__global__ void prep_w_kernel(const float* __restrict__ W) {
    int i = blockIdx.x * 256 + threadIdx.x;
    if (i < KOFF * CIN * COUT) g_w16[i] = __float2half_rn(W[i]);
}

__global__ void prep_idx_kernel(const int* __restrict__ nbr, const int* __restrict__ mask) {
    int i = blockIdx.x * 256 + threadIdx.x;
    if (i < KOFF * NROW) g_idx2[i] = mask[i] ? nbr[i] : NROW;   // masked -> zero row
}

// ---------------- main gather-GEMM kernel ----------------
// 128 threads: A = 128 rows x 8 chunks of 16B -> 8 chunks/thread
//              B = 64 rows x 8 chunks        -> 4 chunks/thread
__device__ __forceinline__ void load_stage(uint32_t sb, int tid, int k, const int* idx8) {
    int s = k & 1;
    uint32_t abuf = sb + OFF_A + s * A_STAGE;
    uint32_t bbuf = sb + OFF_B + s * B_STAGE;
    int ch = tid & 7;
    #pragma unroll
    for (int it = 0; it < 8; it++) {
        int r = it * 16 + (tid >> 3);
        const char* gsrc = (const char*)g_feats16 + ((size_t)idx8[it] * (CIN * 2) + ch * 16);
        cp_async16(abuf + (uint32_t)(r * A_STRIDE + ch * 16), gsrc);
    }
    const char* wsrc = (const char*)g_w16 + (size_t)k * (CIN * COUT * 2);
    #pragma unroll
    for (int it = 0; it < 4; it++) {
        int r = it * 16 + (tid >> 3);
        cp_async16(bbuf + (uint32_t)(r * B_STRIDE + ch * 16), wsrc + r * 128 + ch * 16);
    }
    cp_commit();
}

__global__ void __launch_bounds__(128) conv_mma_kernel() {
    extern __shared__ char smem[];
    uint32_t sb = smem_u32(smem);
    int tid = threadIdx.x, lane = tid & 31, wid = tid >> 5;   // 4 warps, warp tile 32(M) x 64(N)
    int m0 = blockIdx.x * TILE_M;

    float d[2][8][4];
    #pragma unroll
    for (int i = 0; i < 2; i++)
        #pragma unroll
        for (int j = 0; j < 8; j++)
            #pragma unroll
            for (int l = 0; l < 4; l++) d[i][j][l] = 0.f;

    // index prefetch registers (8 rows per thread)
    int idxn[8];
    {
        int idxc[8];
        #pragma unroll
        for (int it = 0; it < 8; it++) {
            int m = m0 + it * 16 + (tid >> 3);
            idxc[it] = (m < NROW) ? __ldg(&g_idx2[m]) : NROW;
        }
        load_stage(sb, tid, 0, idxc);
    }
    #pragma unroll
    for (int it = 0; it < 8; it++) {
        int m = m0 + it * 16 + (tid >> 3);
        idxn[it] = (m < NROW) ? __ldg(&g_idx2[NROW + m]) : NROW;
    }

    // per-thread invariant ldmatrix offsets (within a stage)
    uint32_t a_off = (uint32_t)((wid * 32 + (lane & 15)) * A_STRIDE + (lane >> 4) * 16);
    uint32_t b_off = (uint32_t)((lane & 15) * B_STRIDE + (lane >> 4) * 16);

    #pragma unroll 1
    for (int k = 0; k < KOFF; k++) {
        if (k < KOFF - 1) load_stage(sb, tid, k + 1, idxn);
        if (k < KOFF - 2) {   // prefetch indices for k+2 (latency hidden across this iter)
            #pragma unroll
            for (int it = 0; it < 8; it++) {
                int m = m0 + it * 16 + (tid >> 3);
                idxn[it] = (m < NROW) ? __ldg(&g_idx2[(k + 2) * NROW + m]) : NROW;
            }
        }
        if (k < KOFF - 1) asm volatile("cp.async.wait_group 1;" ::: "memory");
        else              asm volatile("cp.async.wait_group 0;" ::: "memory");
        __syncthreads();

        uint32_t abase = sb + OFF_A + (k & 1) * A_STAGE + a_off;
        uint32_t bbase = sb + OFF_B + (k & 1) * B_STAGE + b_off;
        #pragma unroll
        for (int kk = 0; kk < 4; kk++) {      // K = 64 in 4 x k16
            uint32_t a0 = abase + kk * 32;
            uint32_t bk = bbase + kk * 16 * B_STRIDE;
            uint32_t afr[2][4], bfr[4][4];
            ldmatrix_x4(afr[0], a0);
            ldmatrix_x4(afr[1], a0 + 16 * A_STRIDE);
            #pragma unroll
            for (int jb = 0; jb < 4; jb++) ldmatrix_x4_t(bfr[jb], bk + jb * 32);
            #pragma unroll
            for (int mi = 0; mi < 2; mi++)
                #pragma unroll
                for (int nn = 0; nn < 8; nn++)
                    mma16816(d[mi][nn], afr[mi],
                             bfr[nn >> 1][(nn & 1) * 2], bfr[nn >> 1][(nn & 1) * 2 + 1]);
        }
        __syncthreads();   // protect buffer reuse by next iteration's loads
    }

    // ---------------- epilogue ----------------
    float* stats = (float*)smem;   // [64 ch][129] padded
    {
        int r0 = wid * 32 + (lane >> 2);
        int c0 = (lane & 3) * 2;
        #pragma unroll
        for (int mi = 0; mi < 2; mi++)
            #pragma unroll
            for (int nn = 0; nn < 8; nn++) {
                int r = r0 + mi * 16;
                int c = c0 + nn * 8;
                stats[(c + 0) * 129 + r]     = d[mi][nn][0];
                stats[(c + 1) * 129 + r]     = d[mi][nn][1];
                stats[(c + 0) * 129 + r + 8] = d[mi][nn][2];
                stats[(c + 1) * 129 + r + 8] = d[mi][nn][3];
            }
    }
    __syncthreads();

    // coalesced conv write: 2048 float4 / 128 thr = 16 iters
    #pragma unroll
    for (int it = 0; it < 16; it++) {
        int idx = it * 128 + tid;
        int r = idx >> 4, c4 = idx & 15;
        int m = m0 + r;
        if (m < NROW) {
            float4 v;
            v.x = stats[(c4 * 4 + 0) * 129 + r];
            v.y = stats[(c4 * 4 + 1) * 129 + r];
            v.z = stats[(c4 * 4 + 2) * 129 + r];
            v.w = stats[(c4 * 4 + 3) * 129 + r];
            reinterpret_cast<float4*>(g_conv + (size_t)m * COUT)[c4] = v;
        }
    }

    // per-tile channel sums (fixed order -> deterministic); rows >= NROW are exact zeros
    {
        int c = tid & 63, part = tid >> 6;     // 64 channels x 2 row-groups of 64
        float s = 0.f, s2 = 0.f;
        #pragma unroll
        for (int i = 0; i < 64; i++) {
            float v = stats[c * 129 + part * 64 + i];
            s += v; s2 += v * v;
        }
        float* ps = (float*)(smem + OFF_PS);
        ps[part * 64 + c]       = s;
        ps[128 + part * 64 + c] = s2;
    }
    __syncthreads();
    if (tid < 64) {
        const float* ps = (const float*)(smem + OFF_PS);
        float S  = ps[tid] + ps[64 + tid];
        float S2 = ps[128 + tid] + ps[192 + tid];
        g_partials[blockIdx.x * 128 + tid]      = S;
        g_partials[blockIdx.x * 128 + 64 + tid] = S2;
    }
}

// ---------------- BN stats finalize (single block, deterministic) ----------------
__global__ void bn_stats_kernel(const float* __restrict__ gamma, const float* __restrict__ beta) {
    __shared__ float sh[256];
    int tid = threadIdx.x;
    int c = tid & 127, seg = tid >> 7;         // 2 segments over tiles
    const int half = (NTILES + 1) / 2;         // 782
    int lo = seg * half;
    int hi = lo + half; if (hi > NTILES) hi = NTILES;
    float s = 0.f;
    #pragma unroll 4
    for (int t = lo; t < hi; t++) s += g_partials[t * 128 + c];
    sh[tid] = s;
    __syncthreads();
    if (tid < 64) {
        float S  = sh[tid]      + sh[128 + tid];       // fixed order
        float S2 = sh[64 + tid] + sh[192 + tid];
        const float invN = 1.0f / (float)NROW;
        float mean = S * invN;
        float var  = S2 * invN - mean * mean;
        float inv  = rsqrtf(var + 1e-5f);
        float sc   = inv * gamma[tid];
        g_bn[tid]      = sc;
        g_bn[64 + tid] = beta[tid] - mean * sc;
    }
}

// ---------------- BN apply + ReLU ----------------
__global__ void bn_apply_kernel(float* __restrict__ out) {
    int i = blockIdx.x * 256 + threadIdx.x;    // one float4
    if (i >= NROW * (COUT / 4)) return;
    int c = (i & 15) << 2;
    float4 v = reinterpret_cast<const float4*>(g_conv)[i];
    float4 r;
    r.x = fmaxf(fmaf(v.x, __ldg(&g_bn[c + 0]), __ldg(&g_bn[64 + c + 0])), 0.f);
    r.y = fmaxf(fmaf(v.y, __ldg(&g_bn[c + 1]), __ldg(&g_bn[64 + c + 1])), 0.f);
    r.z = fmaxf(fmaf(v.z, __ldg(&g_bn[c + 2]), __ldg(&g_bn[64 + c + 2])), 0.f);
    r.w = fmaxf(fmaf(v.w, __ldg(&g_bn[c + 3]), __ldg(&g_bn[64 + c + 3])), 0.f);
    reinterpret_cast<float4*>(out)[i] = r;
}

// ---------------- launch ----------------
extern "C" void kernel_launch(void* const* d_in, const int* in_sizes, int n_in,
                              void* d_out, int out_size) {
    const float* feats = (const float*)d_in[0];
    const float* W     = (const float*)d_in[1];
    const float* gamma = (const float*)d_in[2];
    const float* beta  = (const float*)d_in[3];
    const int*   nbr   = (const int*)d_in[4];
    const int*   mask  = (const int*)d_in[5];
    float* out = (float*)d_out;

    cudaFuncSetAttribute(conv_mma_kernel, cudaFuncAttributeMaxDynamicSharedMemorySize, SMEM_BYTES);

    prep_feats_kernel<<<(NROW * (CIN / 4) + (CIN / 4) + 255) / 256, 256>>>(feats);
    prep_w_kernel<<<(KOFF * CIN * COUT + 255) / 256, 256>>>(W);
    prep_idx_kernel<<<(KOFF * NROW + 255) / 256, 256>>>(nbr, mask);
    conv_mma_kernel<<<NTILES, 128, SMEM_BYTES>>>();
    bn_stats_kernel<<<1, 256>>>(gamma, beta);
    bn_apply_kernel<<<(NROW * (COUT / 4) + 255) / 256, 256>>>(out);
}